// round 1
// baseline (speedup 1.0000x reference)
#include <cuda_runtime.h>
#include <cstdint>

#define D 128
#define NN 100000
#define EM 400000
#define EW 200000
#define EPS 1e-5f

#define ROWS 64
#define THREADS 256
#define KT 32

// smem layout (floats):
//  xs : ROWS*33        (gathered A tile, padded)
//  ws : 32*128         (W tile)
//  hs : ROWS*132       (hidden / y staging, padded)
//  cv : 4*128          (b1,b2,gamma,beta)
//  idx: 2*ROWS ints
#define XS_OFF 0
#define WS_OFF (ROWS*33)
#define HS_OFF (WS_OFF + 32*128)
#define CV_OFF (HS_OFF + ROWS*132)
#define IDX_OFF (CV_OFF + 4*128)
#define SMEM_BYTES (IDX_OFF*4 + 2*ROWS*4)

// scatter-sum scratch (allocation-free rule: __device__ globals)
__device__ float g_agg_mesh[(size_t)NN * D];
__device__ float g_agg_world[(size_t)NN * D];

// ---------- packed f32x2 helpers (sm_103a FFMA2: 2x fp32 throughput) ----------
__device__ __forceinline__ unsigned long long bcast2(float a) {
    unsigned long long r;
    unsigned u = __float_as_uint(a);
    asm("mov.b64 %0, {%1, %1};" : "=l"(r) : "r"(u));
    return r;
}
__device__ __forceinline__ void ffma2(unsigned long long& d,
                                      unsigned long long a,
                                      unsigned long long b) {
    asm("fma.rn.f32x2 %0, %1, %2, %0;" : "+l"(d) : "l"(a), "l"(b));
}
__device__ __forceinline__ void unpack2(unsigned long long v, float& lo, float& hi) {
    unsigned ulo, uhi;
    asm("mov.b64 {%0, %1}, %2;" : "=r"(ulo), "=r"(uhi) : "l"(v));
    lo = __uint_as_float(ulo);
    hi = __uint_as_float(uhi);
}

__global__ void zero_agg_kernel(float* __restrict__ aggM, float* __restrict__ aggW) {
    size_t i = (size_t)blockIdx.x * blockDim.x + threadIdx.x;
    size_t n4 = (size_t)NN * D / 4;
    float4 z = make_float4(0.f, 0.f, 0.f, 0.f);
    if (i < n4) {
        ((float4*)aggM)[i] = z;
        ((float4*)aggW)[i] = z;
    }
}

// EDGE=true : rows are edges; A = [nf[snd], nf[rcv], ef]; epilogue scatters y into aggOut
//             and writes y + ef.
// EDGE=false: rows are nodes; A = [nf, aggA, aggB]; epilogue writes y + nf.
template <bool EDGE>
__global__ void __launch_bounds__(THREADS)
mlp_ln_kernel(const float* __restrict__ nf,
              const int*   __restrict__ senders,
              const int*   __restrict__ receivers,
              const float* __restrict__ ef,
              const float* __restrict__ aggA,
              const float* __restrict__ aggB,
              const float* __restrict__ W1, const float* __restrict__ b1,
              const float* __restrict__ W2, const float* __restrict__ b2,
              const float* __restrict__ gam, const float* __restrict__ bet,
              float* __restrict__ aggOut,
              float* __restrict__ out,
              int nRows) {
    extern __shared__ float sm[];
    float* xs = sm + XS_OFF;
    float* ws = sm + WS_OFF;
    float* hs = sm + HS_OFF;
    float* cv = sm + CV_OFF;
    int*   sidx = (int*)(sm + IDX_OFF);
    int*   ridx = sidx + ROWS;

    const int tid = threadIdx.x;
    const int r0  = blockIdx.x * ROWS;

    if (tid < 128) {
        cv[tid]       = b1[tid];
        cv[128 + tid] = b2[tid];
        cv[256 + tid] = gam[tid];
        cv[384 + tid] = bet[tid];
    }
    if (EDGE && tid < ROWS) {
        int rr = r0 + tid;
        int s = 0, rc = 0;
        if (rr < nRows) { s = senders[rr]; rc = receivers[rr]; }
        sidx[tid] = s;
        ridx[tid] = rc;
    }
    __syncthreads();

    const int trow = (tid >> 4) * 4;    // 0..60
    const int tcol = (tid & 15) * 8;    // 0..120

    unsigned long long acc[4][4];
#pragma unroll
    for (int i = 0; i < 4; i++)
#pragma unroll
        for (int p = 0; p < 4; p++) acc[i][p] = 0ULL;

    // ---------------- GEMM1: [64 x 384] @ [384 x 128] ----------------
    for (int kt = 0; kt < 3 * D; kt += KT) {
        // gather A tile: e = tid + j*256 -> kk = e&31, r = e>>5 (coalesced per row)
#pragma unroll
        for (int j = 0; j < 8; j++) {
            int e  = tid + j * THREADS;
            int kk = e & 31;
            int r  = e >> 5;
            int k  = kt + kk;
            int gr = r0 + r;
            if (gr >= nRows) gr = nRows - 1;
            float v;
            if (EDGE) {
                if (k < D)            v = nf[(size_t)sidx[r] * D + k];
                else if (k < 2 * D)   v = nf[(size_t)ridx[r] * D + (k - D)];
                else                  v = ef[(size_t)gr * D + (k - 2 * D)];
            } else {
                if (k < D)            v = nf[(size_t)gr * D + k];
                else if (k < 2 * D)   v = aggA[(size_t)gr * D + (k - D)];
                else                  v = aggB[(size_t)gr * D + (k - 2 * D)];
            }
            xs[r * 33 + kk] = v;
        }
        // W1 tile (float4 coalesced)
#pragma unroll
        for (int j = 0; j < 4; j++) {
            int e4 = tid + j * THREADS;
            int kk = e4 >> 5;
            int n4 = e4 & 31;
            ((float4*)ws)[kk * 32 + n4] = ((const float4*)W1)[(size_t)(kt + kk) * 32 + n4];
        }
        __syncthreads();
#pragma unroll
        for (int kk = 0; kk < KT; kk++) {
            const ulonglong2 wa = *(const ulonglong2*)(ws + kk * 128 + tcol);
            const ulonglong2 wb = *(const ulonglong2*)(ws + kk * 128 + tcol + 4);
            unsigned long long xp0 = bcast2(xs[(trow + 0) * 33 + kk]);
            unsigned long long xp1 = bcast2(xs[(trow + 1) * 33 + kk]);
            unsigned long long xp2 = bcast2(xs[(trow + 2) * 33 + kk]);
            unsigned long long xp3 = bcast2(xs[(trow + 3) * 33 + kk]);
            ffma2(acc[0][0], xp0, wa.x); ffma2(acc[0][1], xp0, wa.y);
            ffma2(acc[0][2], xp0, wb.x); ffma2(acc[0][3], xp0, wb.y);
            ffma2(acc[1][0], xp1, wa.x); ffma2(acc[1][1], xp1, wa.y);
            ffma2(acc[1][2], xp1, wb.x); ffma2(acc[1][3], xp1, wb.y);
            ffma2(acc[2][0], xp2, wa.x); ffma2(acc[2][1], xp2, wa.y);
            ffma2(acc[2][2], xp2, wb.x); ffma2(acc[2][3], xp2, wb.y);
            ffma2(acc[3][0], xp3, wa.x); ffma2(acc[3][1], xp3, wa.y);
            ffma2(acc[3][2], xp3, wb.x); ffma2(acc[3][3], xp3, wb.y);
        }
        __syncthreads();
    }

    // h = relu(. + b1) -> hs
#pragma unroll
    for (int i = 0; i < 4; i++) {
        int row = trow + i;
#pragma unroll
        for (int p = 0; p < 4; p++) {
            float lo, hi;
            unpack2(acc[i][p], lo, hi);
            lo = fmaxf(lo + cv[tcol + 2 * p], 0.f);
            hi = fmaxf(hi + cv[tcol + 2 * p + 1], 0.f);
            *(float2*)&hs[row * 132 + tcol + 2 * p] = make_float2(lo, hi);
            acc[i][p] = 0ULL;
        }
    }
    __syncthreads();

    // ---------------- GEMM2: [64 x 128] @ [128 x 128] ----------------
    for (int kt = 0; kt < D; kt += KT) {
#pragma unroll
        for (int j = 0; j < 4; j++) {
            int e4 = tid + j * THREADS;
            int kk = e4 >> 5;
            int n4 = e4 & 31;
            ((float4*)ws)[kk * 32 + n4] = ((const float4*)W2)[(size_t)(kt + kk) * 32 + n4];
        }
        __syncthreads();
#pragma unroll
        for (int kk = 0; kk < KT; kk++) {
            const ulonglong2 wa = *(const ulonglong2*)(ws + kk * 128 + tcol);
            const ulonglong2 wb = *(const ulonglong2*)(ws + kk * 128 + tcol + 4);
            unsigned long long xp0 = bcast2(hs[(trow + 0) * 132 + kt + kk]);
            unsigned long long xp1 = bcast2(hs[(trow + 1) * 132 + kt + kk]);
            unsigned long long xp2 = bcast2(hs[(trow + 2) * 132 + kt + kk]);
            unsigned long long xp3 = bcast2(hs[(trow + 3) * 132 + kt + kk]);
            ffma2(acc[0][0], xp0, wa.x); ffma2(acc[0][1], xp0, wa.y);
            ffma2(acc[0][2], xp0, wb.x); ffma2(acc[0][3], xp0, wb.y);
            ffma2(acc[1][0], xp1, wa.x); ffma2(acc[1][1], xp1, wa.y);
            ffma2(acc[1][2], xp1, wb.x); ffma2(acc[1][3], xp1, wb.y);
            ffma2(acc[2][0], xp2, wa.x); ffma2(acc[2][1], xp2, wa.y);
            ffma2(acc[2][2], xp2, wb.x); ffma2(acc[2][3], xp2, wb.y);
            ffma2(acc[3][0], xp3, wa.x); ffma2(acc[3][1], xp3, wa.y);
            ffma2(acc[3][2], xp3, wb.x); ffma2(acc[3][3], xp3, wb.y);
        }
        __syncthreads();
    }

    // ---------------- LayerNorm over 128 cols (16 lanes per row) ----------------
    float vals[4][8];
#pragma unroll
    for (int i = 0; i < 4; i++) {
        float s = 0.f, sq = 0.f;
#pragma unroll
        for (int p = 0; p < 4; p++) {
            float lo, hi;
            unpack2(acc[i][p], lo, hi);
            lo += cv[128 + tcol + 2 * p];
            hi += cv[128 + tcol + 2 * p + 1];
            vals[i][2 * p] = lo;
            vals[i][2 * p + 1] = hi;
            s += lo + hi;
            sq += lo * lo + hi * hi;
        }
#pragma unroll
        for (int m = 1; m < 16; m <<= 1) {
            s  += __shfl_xor_sync(0xffffffffu, s, m);
            sq += __shfl_xor_sync(0xffffffffu, sq, m);
        }
        float mean = s * (1.f / D);
        float var  = sq * (1.f / D) - mean * mean;
        float rstd = rsqrtf(var + EPS);
        int row = trow + i;
#pragma unroll
        for (int c = 0; c < 8; c++) {
            int col = tcol + c;
            float y = cv[256 + col] * (vals[i][c] - mean) * rstd + cv[384 + col];
            hs[row * 132 + col] = y;
        }
    }
    __syncthreads();

    // ---------------- epilogue: scatter / residual / store (coalesced) ----------------
#pragma unroll 4
    for (int j = 0; j < (ROWS * D) / THREADS; j++) {
        int e = tid + j * THREADS;
        int r = e >> 7;
        int c = e & 127;
        int gr = r0 + r;
        if (gr < nRows) {
            float y = hs[r * 132 + c];
            size_t gi = (size_t)gr * D + c;
            if (EDGE) {
                atomicAdd(&aggOut[(size_t)ridx[r] * D + c], y);
                out[gi] = y + ef[gi];
            } else {
                out[gi] = y + nf[gi];
            }
        }
    }
}

extern "C" void kernel_launch(void* const* d_in, const int* in_sizes, int n_in,
                              void* d_out, int out_size) {
    (void)in_sizes; (void)n_in; (void)out_size;
    const float* nf   = (const float*)d_in[0];
    const int*   msnd = (const int*)d_in[1];
    const int*   mrcv = (const int*)d_in[2];
    const float* mf   = (const float*)d_in[3];
    const int*   wsnd = (const int*)d_in[4];
    const int*   wrcv = (const int*)d_in[5];
    const float* wf   = (const float*)d_in[6];

    const float* meW1 = (const float*)d_in[7];
    const float* meb1 = (const float*)d_in[8];
    const float* meW2 = (const float*)d_in[9];
    const float* meb2 = (const float*)d_in[10];
    const float* meg  = (const float*)d_in[11];
    const float* mebt = (const float*)d_in[12];

    const float* weW1 = (const float*)d_in[13];
    const float* web1 = (const float*)d_in[14];
    const float* weW2 = (const float*)d_in[15];
    const float* web2 = (const float*)d_in[16];
    const float* weg  = (const float*)d_in[17];
    const float* webt = (const float*)d_in[18];

    const float* nmW1 = (const float*)d_in[19];
    const float* nmb1 = (const float*)d_in[20];
    const float* nmW2 = (const float*)d_in[21];
    const float* nmb2 = (const float*)d_in[22];
    const float* nmg  = (const float*)d_in[23];
    const float* nmbt = (const float*)d_in[24];

    float* out        = (float*)d_out;
    float* out_nodes  = out;
    float* out_mesh   = out + (size_t)NN * D;
    float* out_world  = out_mesh + (size_t)EM * D;

    float* aggM = nullptr;
    float* aggW = nullptr;
    cudaGetSymbolAddress((void**)&aggM, g_agg_mesh);
    cudaGetSymbolAddress((void**)&aggW, g_agg_world);

    cudaFuncSetAttribute(mlp_ln_kernel<true>,
                         cudaFuncAttributeMaxDynamicSharedMemorySize, SMEM_BYTES);
    cudaFuncSetAttribute(mlp_ln_kernel<false>,
                         cudaFuncAttributeMaxDynamicSharedMemorySize, SMEM_BYTES);

    {
        size_t n4 = (size_t)NN * D / 4;
        int blocks = (int)((n4 + 255) / 256);
        zero_agg_kernel<<<blocks, 256>>>(aggM, aggW);
    }

    mlp_ln_kernel<true><<<EM / ROWS, THREADS, SMEM_BYTES>>>(
        nf, msnd, mrcv, mf, nullptr, nullptr,
        meW1, meb1, meW2, meb2, meg, mebt,
        aggM, out_mesh, EM);

    mlp_ln_kernel<true><<<EW / ROWS, THREADS, SMEM_BYTES>>>(
        nf, wsnd, wrcv, wf, nullptr, nullptr,
        weW1, web1, weW2, web2, weg, webt,
        aggW, out_world, EW);

    mlp_ln_kernel<false><<<(NN + ROWS - 1) / ROWS, THREADS, SMEM_BYTES>>>(
        nf, nullptr, nullptr, nullptr, aggM, aggW,
        nmW1, nmb1, nmW2, nmb2, nmg, nmbt,
        nullptr, out_nodes, NN);
}

// round 3
// speedup vs baseline: 2.3331x; 2.3331x over previous
#include <cuda_runtime.h>
#include <cuda_bf16.h>
#include <cstdint>

#define D 128
#define NN 100000
#define EM 400000
#define EW 200000
#define EPS 1e-5f
#define THREADS 512
#define MTILE 128
#define KC 64
#define AST 72                   // row stride in halves (conflict-free: 36 words, +4 banks/row)
#define TILE_H 9216              // 128*72 halves per half-tile
#define TILE_B 18432             // bytes per half-tile

// ---------------- smem layout (bytes) ----------------
#define SM_A   0
#define SM_AL  18432
#define SM_B   36864
#define SM_BL  55296
#define SM_H   73728             // Hh c0 | Hh c1 | Hl c0 | Hl c1 (18432 each)
#define SM_CV  147456            // 512 floats: b1,b2,gamma,beta
#define SM_IDX 149504            // 256 ints: sidx, ridx
#define SM_STAT 150528           // statS[512], statQ[512], mean[128], rstd[128]
#define SM_TOTAL 155648
#define HS_STRIDE 129            // hs aliases SM_H: 128*129*4 = 66048 <= 73728

// ---------------- device scratch ----------------
__device__ float g_agg_mesh[(size_t)NN * D];
__device__ float g_agg_world[(size_t)NN * D];
// per mlp: 8 K-chunks (6 for W1, 2 for W2) x {hi,lo} x [128 n][72 k] bf16
__device__ __nv_bfloat16 g_Wimg[3 * 8 * 2 * TILE_H];

// ---------------- helpers ----------------
__device__ __forceinline__ uint32_t smem_u32(const void* p) {
    uint32_t a;
    asm("{ .reg .u64 t; cvta.to.shared.u64 t, %1; cvt.u32.u64 %0, t; }" : "=r"(a) : "l"(p));
    return a;
}
__device__ __forceinline__ uint32_t lds_u32(uint32_t a) {
    uint32_t v; asm volatile("ld.shared.b32 %0, [%1];" : "=r"(v) : "r"(a)); return v;
}
#define MMA_BF16(d, a, b0, b1) \
    asm volatile("mma.sync.aligned.m16n8k16.row.col.f32.bf16.bf16.f32 " \
        "{%0,%1,%2,%3}, {%4,%5,%6,%7}, {%8,%9}, {%0,%1,%2,%3};" \
        : "+f"((d)[0]), "+f"((d)[1]), "+f"((d)[2]), "+f"((d)[3]) \
        : "r"((a)[0]), "r"((a)[1]), "r"((a)[2]), "r"((a)[3]), "r"(b0), "r"(b1))

__device__ __forceinline__ void split_pack(float x, float y, uint32_t& hp, uint32_t& lp) {
    __nv_bfloat16 h0 = __float2bfloat16(x);
    __nv_bfloat16 h1 = __float2bfloat16(y);
    __nv_bfloat16 l0 = __float2bfloat16(x - __bfloat162float(h0));
    __nv_bfloat16 l1 = __float2bfloat16(y - __bfloat162float(h1));
    hp = (uint32_t)__bfloat16_as_ushort(h0) | ((uint32_t)__bfloat16_as_ushort(h1) << 16);
    lp = (uint32_t)__bfloat16_as_ushort(l0) | ((uint32_t)__bfloat16_as_ushort(l1) << 16);
}

// one K=64 chunk of MMA: A (rows) hi/lo at aH/aL, B (n-major) hi/lo at bH/bL
__device__ __forceinline__ void gemm_chunk(uint32_t aH, uint32_t aL,
                                           uint32_t bH, uint32_t bL,
                                           float acc[2][4][4],
                                           int wM, int wN, int lane) {
    const int g = lane >> 2, c = lane & 3;
#pragma unroll
    for (int ks = 0; ks < 4; ks++) {
        const int kcol = ks * 16 + c * 2;
        uint32_t ah[2][4], al[2][4];
#pragma unroll
        for (int mt = 0; mt < 2; mt++) {
            int r = wM * 32 + mt * 16 + g;
            uint32_t o0 = (uint32_t)(r * AST + kcol) * 2;
            uint32_t o1 = (uint32_t)((r + 8) * AST + kcol) * 2;
            ah[mt][0] = lds_u32(aH + o0);
            ah[mt][1] = lds_u32(aH + o1);
            ah[mt][2] = lds_u32(aH + o0 + 16);
            ah[mt][3] = lds_u32(aH + o1 + 16);
            al[mt][0] = lds_u32(aL + o0);
            al[mt][1] = lds_u32(aL + o1);
            al[mt][2] = lds_u32(aL + o0 + 16);
            al[mt][3] = lds_u32(aL + o1 + 16);
        }
#pragma unroll
        for (int nt = 0; nt < 4; nt++) {
            int n = wN * 32 + nt * 8 + g;
            uint32_t ob = (uint32_t)(n * AST + kcol) * 2;
            uint32_t bh0 = lds_u32(bH + ob);
            uint32_t bh1 = lds_u32(bH + ob + 16);
            uint32_t bl0 = lds_u32(bL + ob);
            uint32_t bl1 = lds_u32(bL + ob + 16);
#pragma unroll
            for (int mt = 0; mt < 2; mt++) {
                MMA_BF16(acc[mt][nt], ah[mt], bh0, bh1);   // hi*hi
                MMA_BF16(acc[mt][nt], ah[mt], bl0, bl1);   // hi*lo
                MMA_BF16(acc[mt][nt], al[mt], bh0, bh1);   // lo*hi
            }
        }
    }
}

// ---------------- prep: split weights into [n][k] bf16 hi/lo chunk images ----------------
__global__ void prep_kernel(const float* __restrict__ W1, const float* __restrict__ W2,
                            __nv_bfloat16* __restrict__ img) {
    int idx = blockIdx.x * blockDim.x + threadIdx.x;   // 0..65535
    int chunk = idx >> 13;
    int rem = idx & 8191;
    int n = rem >> 6;
    int kk = rem & 63;
    float v;
    if (chunk < 6) v = W1[(size_t)(chunk * 64 + kk) * 128 + n];
    else           v = W2[(size_t)((chunk - 6) * 64 + kk) * 128 + n];
    __nv_bfloat16 hi = __float2bfloat16(v);
    __nv_bfloat16 lo = __float2bfloat16(v - __bfloat162float(hi));
    size_t base = (size_t)chunk * 2 * TILE_H + (size_t)n * AST + kk;
    img[base] = hi;
    img[base + TILE_H] = lo;
}

__global__ void zero_agg_kernel(float* __restrict__ aggM, float* __restrict__ aggW) {
    size_t i = (size_t)blockIdx.x * blockDim.x + threadIdx.x;
    size_t n4 = (size_t)NN * D / 4;
    float4 z = make_float4(0.f, 0.f, 0.f, 0.f);
    if (i < n4) { ((float4*)aggM)[i] = z; ((float4*)aggW)[i] = z; }
}

// ---------------- fused MLP+LN block kernel ----------------
template <bool EDGE>
__global__ void __launch_bounds__(THREADS, 1)
mlp_ln_mma_kernel(const float* __restrict__ nf,
                  const int*   __restrict__ senders,
                  const int*   __restrict__ receivers,
                  const float* __restrict__ ef,
                  const float* __restrict__ aggA,
                  const float* __restrict__ aggB,
                  const __nv_bfloat16* __restrict__ img,
                  const float* __restrict__ b1, const float* __restrict__ b2,
                  const float* __restrict__ gam, const float* __restrict__ bet,
                  float* __restrict__ aggOut,
                  float* __restrict__ out,
                  int nRows) {
    extern __shared__ char sm[];
    float* cv    = (float*)(sm + SM_CV);
    int*   sidx  = (int*)(sm + SM_IDX);
    int*   ridx  = sidx + MTILE;
    float* statS = (float*)(sm + SM_STAT);          // [4][128]
    float* statQ = statS + 512;                     // [4][128]
    float* meanv = statQ + 512;                     // [128]
    float* rstdv = meanv + 128;                     // [128]
    float* hs    = (float*)(sm + SM_H);             // alias, live only after GEMM2

    const uint32_t smb = smem_u32(sm);
    const int tid = threadIdx.x;
    const int wid = tid >> 5;
    const int lane = tid & 31;
    const int wM = wid >> 2;       // 0..3  (rows 32*wM .. +31)
    const int wN = wid & 3;        // 0..3  (cols 32*wN .. +31)
    const int g = lane >> 2, cl = lane & 3;
    const int r0 = blockIdx.x * MTILE;

    if (tid < 128) {
        cv[tid]       = b1[tid];
        cv[128 + tid] = b2[tid];
        cv[256 + tid] = gam[tid];
        cv[384 + tid] = bet[tid];
        if (EDGE) {
            int rr = r0 + tid;
            if (rr >= nRows) rr = nRows - 1;
            sidx[tid] = senders[rr];
            ridx[tid] = receivers[rr];
        }
    }
    __syncthreads();

    float acc[2][4][4];
#pragma unroll
    for (int mt = 0; mt < 2; mt++)
#pragma unroll
        for (int nt = 0; nt < 4; nt++)
#pragma unroll
            for (int j = 0; j < 4; j++) acc[mt][nt][j] = 0.f;

    // ================= GEMM1: 6 K-chunks of 64 =================
    for (int c = 0; c < 6; c++) {
        // gather + split A chunk: 128 rows x 64 cols (4096 float2)
#pragma unroll
        for (int j = 0; j < 8; j++) {
            int e = j * THREADS + tid;
            int row = e >> 5;
            int cp = e & 31;
            int gr = r0 + row;
            if (gr >= nRows) gr = nRows - 1;
            const float* p;
            int col0;
            if (EDGE) {
                if (c < 2)      { p = nf + (size_t)sidx[row] * D; col0 = c * 64; }
                else if (c < 4) { p = nf + (size_t)ridx[row] * D; col0 = (c - 2) * 64; }
                else            { p = ef + (size_t)gr * D;        col0 = (c - 4) * 64; }
            } else {
                const float* srcs = c < 2 ? nf : (c < 4 ? aggA : aggB);
                p = srcs + (size_t)gr * D;
                col0 = (c & 1) * 64;
                if (c >= 2) col0 = ((c - 2) & 1) * 64;
                if (c >= 4) col0 = ((c - 4) & 1) * 64;
            }
            float2 v = *(const float2*)(p + col0 + cp * 2);
            uint32_t hp, lp;
            split_pack(v.x, v.y, hp, lp);
            uint32_t off = (uint32_t)(row * AST + 2 * cp) * 2;
            *(uint32_t*)(sm + SM_A  + off) = hp;
            *(uint32_t*)(sm + SM_AL + off) = lp;
        }
        // copy W1 chunk (hi+lo contiguous, 36864B)
        {
            const uint4* src = (const uint4*)((const char*)img + (size_t)c * 2 * TILE_B);
            uint4* dst = (uint4*)(sm + SM_B);
            for (int j = tid; j < 2304; j += THREADS) dst[j] = src[j];
        }
        __syncthreads();
        gemm_chunk(smb + SM_A, smb + SM_AL, smb + SM_B, smb + SM_BL, acc, wM, wN, lane);
        __syncthreads();
    }

    // ================= h = relu(D1 + b1) -> bf16 hi/lo into H =================
#pragma unroll
    for (int mt = 0; mt < 2; mt++)
#pragma unroll
        for (int nt = 0; nt < 4; nt++)
#pragma unroll
            for (int h = 0; h < 2; h++) {
                int row = wM * 32 + mt * 16 + h * 8 + g;
                int col = wN * 32 + nt * 8 + 2 * cl;
                float v0 = fmaxf(acc[mt][nt][2 * h]     + cv[col],     0.f);
                float v1 = fmaxf(acc[mt][nt][2 * h + 1] + cv[col + 1], 0.f);
                uint32_t hp, lp;
                split_pack(v0, v1, hp, lp);
                int hc = col >> 6;              // which K-chunk of GEMM2
                uint32_t off = (uint32_t)(row * AST + (col & 63)) * 2;
                *(uint32_t*)(sm + SM_H + hc * TILE_B + off) = hp;
                *(uint32_t*)(sm + SM_H + 2 * TILE_B + hc * TILE_B + off) = lp;
            }
#pragma unroll
    for (int mt = 0; mt < 2; mt++)
#pragma unroll
        for (int nt = 0; nt < 4; nt++)
#pragma unroll
            for (int j = 0; j < 4; j++) acc[mt][nt][j] = 0.f;

    // ================= GEMM2: 2 K-chunks of 64 (A = H) =================
    for (int c2 = 0; c2 < 2; c2++) {
        __syncthreads();   // H writes done (c2==0) / previous chunk's mma done
        {
            const uint4* src = (const uint4*)((const char*)img + (size_t)(6 + c2) * 2 * TILE_B);
            uint4* dst = (uint4*)(sm + SM_B);
            for (int j = tid; j < 2304; j += THREADS) dst[j] = src[j];
        }
        __syncthreads();
        gemm_chunk(smb + SM_H + c2 * TILE_B, smb + SM_H + 2 * TILE_B + c2 * TILE_B,
                   smb + SM_B, smb + SM_BL, acc, wM, wN, lane);
    }
    __syncthreads();       // all mma done; H becomes hs staging

    // ================= bias2 + LN stats =================
#pragma unroll
    for (int mt = 0; mt < 2; mt++)
#pragma unroll
        for (int nt = 0; nt < 4; nt++)
#pragma unroll
            for (int j = 0; j < 4; j++) {
                int col = wN * 32 + nt * 8 + 2 * cl + (j & 1);
                acc[mt][nt][j] += cv[128 + col];
            }
#pragma unroll
    for (int mt = 0; mt < 2; mt++)
#pragma unroll
        for (int h = 0; h < 2; h++) {
            float s = 0.f, q = 0.f;
#pragma unroll
            for (int nt = 0; nt < 4; nt++) {
                float v0 = acc[mt][nt][2 * h], v1 = acc[mt][nt][2 * h + 1];
                s += v0 + v1;
                q += v0 * v0 + v1 * v1;
            }
            s += __shfl_xor_sync(0xffffffffu, s, 1);
            s += __shfl_xor_sync(0xffffffffu, s, 2);
            q += __shfl_xor_sync(0xffffffffu, q, 1);
            q += __shfl_xor_sync(0xffffffffu, q, 2);
            if (cl == 0) {
                int r = wM * 32 + mt * 16 + h * 8 + g;
                statS[wN * 128 + r] = s;
                statQ[wN * 128 + r] = q;
            }
        }
    __syncthreads();
    if (tid < 128) {
        float s = statS[tid] + statS[128 + tid] + statS[256 + tid] + statS[384 + tid];
        float q = statQ[tid] + statQ[128 + tid] + statQ[256 + tid] + statQ[384 + tid];
        float mean = s * (1.f / D);
        float var = q * (1.f / D) - mean * mean;
        meanv[tid] = mean;
        rstdv[tid] = rsqrtf(var + EPS);
    }
    __syncthreads();

    // ================= LN apply -> hs =================
#pragma unroll
    for (int mt = 0; mt < 2; mt++)
#pragma unroll
        for (int nt = 0; nt < 4; nt++)
#pragma unroll
            for (int j = 0; j < 4; j++) {
                int row = wM * 32 + mt * 16 + ((j >> 1) ? 8 : 0) + g;
                int col = wN * 32 + nt * 8 + 2 * cl + (j & 1);
                float y = cv[256 + col] * (acc[mt][nt][j] - meanv[row]) * rstdv[row] + cv[384 + col];
                hs[row * HS_STRIDE + col] = y;
            }
    __syncthreads();

    // ================= epilogue: residual store + atomic scatter =================
#pragma unroll 4
    for (int j = 0; j < (MTILE * D) / THREADS; j++) {
        int e = j * THREADS + tid;
        int r = e >> 7;
        int c = e & 127;
        int gr = r0 + r;
        if (gr < nRows) {
            float y = hs[r * HS_STRIDE + c];
            size_t gi = (size_t)gr * D + c;
            if (EDGE) {
                atomicAdd(&aggOut[(size_t)ridx[r] * D + c], y);
                out[gi] = y + ef[gi];
            } else {
                out[gi] = y + nf[gi];
            }
        }
    }
}

// ---------------- launch ----------------
extern "C" void kernel_launch(void* const* d_in, const int* in_sizes, int n_in,
                              void* d_out, int out_size) {
    (void)in_sizes; (void)n_in; (void)out_size;
    const float* nf   = (const float*)d_in[0];
    const int*   msnd = (const int*)d_in[1];
    const int*   mrcv = (const int*)d_in[2];
    const float* mf   = (const float*)d_in[3];
    const int*   wsnd = (const int*)d_in[4];
    const int*   wrcv = (const int*)d_in[5];
    const float* wf   = (const float*)d_in[6];

    const float* meW1 = (const float*)d_in[7];
    const float* meb1 = (const float*)d_in[8];
    const float* meW2 = (const float*)d_in[9];
    const float* meb2 = (const float*)d_in[10];
    const float* meg  = (const float*)d_in[11];
    const float* mebt = (const float*)d_in[12];

    const float* weW1 = (const float*)d_in[13];
    const float* web1 = (const float*)d_in[14];
    const float* weW2 = (const float*)d_in[15];
    const float* web2 = (const float*)d_in[16];
    const float* weg  = (const float*)d_in[17];
    const float* webt = (const float*)d_in[18];

    const float* nmW1 = (const float*)d_in[19];
    const float* nmb1 = (const float*)d_in[20];
    const float* nmW2 = (const float*)d_in[21];
    const float* nmb2 = (const float*)d_in[22];
    const float* nmg  = (const float*)d_in[23];
    const float* nmbt = (const float*)d_in[24];

    float* out       = (float*)d_out;
    float* out_nodes = out;
    float* out_mesh  = out + (size_t)NN * D;
    float* out_world = out_mesh + (size_t)EM * D;

    float* aggM = nullptr;
    float* aggW = nullptr;
    __nv_bfloat16* img = nullptr;
    cudaGetSymbolAddress((void**)&aggM, g_agg_mesh);
    cudaGetSymbolAddress((void**)&aggW, g_agg_world);
    cudaGetSymbolAddress((void**)&img, g_Wimg);
    __nv_bfloat16* imgME = img;
    __nv_bfloat16* imgWE = img + (size_t)8 * 2 * TILE_H;
    __nv_bfloat16* imgNM = img + (size_t)16 * 2 * TILE_H;

    cudaFuncSetAttribute(mlp_ln_mma_kernel<true>,
                         cudaFuncAttributeMaxDynamicSharedMemorySize, SM_TOTAL);
    cudaFuncSetAttribute(mlp_ln_mma_kernel<false>,
                         cudaFuncAttributeMaxDynamicSharedMemorySize, SM_TOTAL);

    {
        size_t n4 = (size_t)NN * D / 4;
        zero_agg_kernel<<<(int)((n4 + 255) / 256), 256>>>(aggM, aggW);
    }
    prep_kernel<<<256, 256>>>(meW1, meW2, imgME);
    prep_kernel<<<256, 256>>>(weW1, weW2, imgWE);
    prep_kernel<<<256, 256>>>(nmW1, nmW2, imgNM);

    mlp_ln_mma_kernel<true><<<EM / MTILE, THREADS, SM_TOTAL>>>(
        nf, msnd, mrcv, mf, nullptr, nullptr,
        imgME, meb1, meb2, meg, mebt, aggM, out_mesh, EM);

    mlp_ln_mma_kernel<true><<<(EW + MTILE - 1) / MTILE, THREADS, SM_TOTAL>>>(
        nf, wsnd, wrcv, wf, nullptr, nullptr,
        imgWE, web1, web2, weg, webt, aggW, out_world, EW);

    mlp_ln_mma_kernel<false><<<(NN + MTILE - 1) / MTILE, THREADS, SM_TOTAL>>>(
        nf, nullptr, nullptr, nullptr, aggM, aggW,
        imgNM, nmb1, nmb2, nmg, nmbt, nullptr, out_nodes, NN);
}

// round 4
// speedup vs baseline: 2.9386x; 1.2595x over previous
#include <cuda_runtime.h>
#include <cuda_bf16.h>
#include <cstdint>

#define D 128
#define NN 100000
#define EM 400000
#define EW 200000
#define EPS 1e-5f
#define THREADS 256
#define MTILE 128
#define AST 72                   // row stride in halves (+4 banks/row skew)
#define TILE_H 9216              // 128*72 halves per half-tile
#define TILE_B 18432             // bytes per half-tile

// ---------------- smem layout (bytes) ----------------
// [0,36864)      A-hi | A-lo   (GEMM1)   -> H-hi chunk0 | chunk1 (GEMM2) -> hs (epilogue)
// [36864,73728)  B-hi | B-lo                                             -> hs (epilogue)
// [73728,110592) H-lo chunk0 | chunk1 (GEMM2)          -> stat arrays (epilogue)
// [110592,112640) cv (b1,b2,gamma,beta)
// [112640,113664) idx (sidx,ridx)
#define SM_A    0
#define SM_AL   18432
#define SM_B    36864
#define SM_BL   55296
#define SM_HLO  73728
#define SM_CV   110592
#define SM_IDX  112640
#define SM_TOTAL 113664
#define HS_STRIDE 129            // hs: 128*129*4 = 66048 bytes at offset 0

// ---------------- device scratch ----------------
__device__ float g_agg_mesh[(size_t)NN * D];
__device__ float g_agg_world[(size_t)NN * D];
// per mlp: 8 K-chunks (6 for W1, 2 for W2) x {hi,lo} x [128 n][72 k] bf16
__device__ __nv_bfloat16 g_Wimg[3 * 8 * 2 * TILE_H];

// ---------------- helpers ----------------
__device__ __forceinline__ uint32_t smem_u32(const void* p) {
    uint32_t a;
    asm("{ .reg .u64 t; cvta.to.shared.u64 t, %1; cvt.u32.u64 %0, t; }" : "=r"(a) : "l"(p));
    return a;
}
__device__ __forceinline__ void ldsm_x4(uint32_t r[4], uint32_t addr) {
    asm volatile("ldmatrix.sync.aligned.m8n8.x4.shared.b16 {%0,%1,%2,%3}, [%4];"
        : "=r"(r[0]), "=r"(r[1]), "=r"(r[2]), "=r"(r[3]) : "r"(addr));
}
#define MMA_BF16(d, a, b0, b1) \
    asm volatile("mma.sync.aligned.m16n8k16.row.col.f32.bf16.bf16.f32 " \
        "{%0,%1,%2,%3}, {%4,%5,%6,%7}, {%8,%9}, {%0,%1,%2,%3};" \
        : "+f"((d)[0]), "+f"((d)[1]), "+f"((d)[2]), "+f"((d)[3]) \
        : "r"((a)[0]), "r"((a)[1]), "r"((a)[2]), "r"((a)[3]), "r"(b0), "r"(b1))

__device__ __forceinline__ void split_pack(float x, float y, uint32_t& hp, uint32_t& lp) {
    __nv_bfloat16 h0 = __float2bfloat16(x);
    __nv_bfloat16 h1 = __float2bfloat16(y);
    __nv_bfloat16 l0 = __float2bfloat16(x - __bfloat162float(h0));
    __nv_bfloat16 l1 = __float2bfloat16(y - __bfloat162float(h1));
    hp = (uint32_t)__bfloat16_as_ushort(h0) | ((uint32_t)__bfloat16_as_ushort(h1) << 16);
    lp = (uint32_t)__bfloat16_as_ushort(l0) | ((uint32_t)__bfloat16_as_ushort(l1) << 16);
}

// one K=64 chunk: warp tile 32 rows (wM) x 64 cols (wN); 3-way bf16 split
__device__ __forceinline__ void gemm_chunk(uint32_t aH, uint32_t aL,
                                           uint32_t bH, uint32_t bL,
                                           float acc[2][8][4],
                                           int wM, int wN, int lane) {
    const int i = lane & 7, sel = lane >> 3;
    const int selA = ((sel & 1) << 3) * AST + ((sel >> 1) << 3);   // row+8*(sel&1), k+8*(sel>>1)
    const int selB = ((sel >> 1) << 3) * AST + ((sel & 1) << 3);   // n+8*(sel>>1),  k+8*(sel&1)
#pragma unroll
    for (int ks = 0; ks < 4; ks++) {
        const int k0 = ks * 16;
        uint32_t ah[2][4], al[2][4];
#pragma unroll
        for (int mt = 0; mt < 2; mt++) {
            uint32_t off = (uint32_t)((wM * 32 + mt * 16 + i) * AST + k0 + selA) * 2;
            ldsm_x4(ah[mt], aH + off);
            ldsm_x4(al[mt], aL + off);
        }
#pragma unroll
        for (int p = 0; p < 4; p++) {
            uint32_t offb = (uint32_t)((wN * 64 + p * 16 + i) * AST + k0 + selB) * 2;
            uint32_t bh[4], bl[4];
            ldsm_x4(bh, bH + offb);
            ldsm_x4(bl, bL + offb);
#pragma unroll
            for (int h = 0; h < 2; h++) {
                const int nt = 2 * p + h;
#pragma unroll
                for (int mt = 0; mt < 2; mt++) {
                    MMA_BF16(acc[mt][nt], ah[mt], bh[2 * h], bh[2 * h + 1]);
                    MMA_BF16(acc[mt][nt], ah[mt], bl[2 * h], bl[2 * h + 1]);
                    MMA_BF16(acc[mt][nt], al[mt], bh[2 * h], bh[2 * h + 1]);
                }
            }
        }
    }
}

// ---------------- prep: split weights into [n][k] bf16 hi/lo chunk images ----------------
__global__ void prep_kernel(const float* __restrict__ W1, const float* __restrict__ W2,
                            __nv_bfloat16* __restrict__ img) {
    int idx = blockIdx.x * blockDim.x + threadIdx.x;   // 0..65535
    int chunk = idx >> 13;
    int rem = idx & 8191;
    int n = rem >> 6;
    int kk = rem & 63;
    float v;
    if (chunk < 6) v = W1[(size_t)(chunk * 64 + kk) * 128 + n];
    else           v = W2[(size_t)((chunk - 6) * 64 + kk) * 128 + n];
    __nv_bfloat16 hi = __float2bfloat16(v);
    __nv_bfloat16 lo = __float2bfloat16(v - __bfloat162float(hi));
    size_t base = (size_t)chunk * 2 * TILE_H + (size_t)n * AST + kk;
    img[base] = hi;
    img[base + TILE_H] = lo;
}

__global__ void zero_agg_kernel(float* __restrict__ aggM, float* __restrict__ aggW) {
    size_t i = (size_t)blockIdx.x * blockDim.x + threadIdx.x;
    size_t n4 = (size_t)NN * D / 4;
    float4 z = make_float4(0.f, 0.f, 0.f, 0.f);
    if (i < n4) { ((float4*)aggM)[i] = z; ((float4*)aggW)[i] = z; }
}

// ---------------- fused MLP+LN block kernel ----------------
template <bool EDGE>
__global__ void __launch_bounds__(THREADS, 2)
mlp_ln_mma_kernel(const float* __restrict__ nf,
                  const int*   __restrict__ senders,
                  const int*   __restrict__ receivers,
                  const float* __restrict__ ef,
                  const float* __restrict__ aggA,
                  const float* __restrict__ aggB,
                  const __nv_bfloat16* __restrict__ img,
                  const float* __restrict__ b1, const float* __restrict__ b2,
                  const float* __restrict__ gam, const float* __restrict__ bet,
                  float* __restrict__ aggOut,
                  float* __restrict__ out,
                  int nRows) {
    extern __shared__ char sm[];
    float* cv    = (float*)(sm + SM_CV);
    int*   sidx  = (int*)(sm + SM_IDX);
    int*   ridx  = sidx + MTILE;
    // epilogue-phase aliases (H-lo region dead by then)
    float* statS = (float*)(sm + SM_HLO);           // [2][128]
    float* statQ = statS + 256;                     // [2][128]
    float* meanv = statQ + 256;                     // [128]
    float* rstdv = meanv + 128;                     // [128]
    float* hs    = (float*)sm;                      // aliases A+B regions after GEMM2

    const uint32_t smb = smem_u32(sm);
    const int tid = threadIdx.x;
    const int wid = tid >> 5;
    const int lane = tid & 31;
    const int wM = wid >> 1;       // 0..3 (rows 32*wM..+31)
    const int wN = wid & 1;        // 0..1 (cols 64*wN..+63)
    const int g4 = lane >> 2, cl = lane & 3;
    const int r0 = blockIdx.x * MTILE;

    if (tid < 128) {
        cv[tid]       = b1[tid];
        cv[128 + tid] = b2[tid];
        cv[256 + tid] = gam[tid];
        cv[384 + tid] = bet[tid];
        if (EDGE) {
            int rr = r0 + tid;
            if (rr >= nRows) rr = nRows - 1;
            sidx[tid] = senders[rr];
            ridx[tid] = receivers[rr];
        }
    }
    __syncthreads();

    float acc[2][8][4];
#pragma unroll
    for (int mt = 0; mt < 2; mt++)
#pragma unroll
        for (int nt = 0; nt < 8; nt++)
#pragma unroll
            for (int j = 0; j < 4; j++) acc[mt][nt][j] = 0.f;

    // ================= GEMM1: 6 K-chunks of 64 =================
    for (int c = 0; c < 6; c++) {
        // gather + split A chunk: 128 rows x 64 cols (4096 float2)
        const int src = c >> 1;
        const int col0 = (c & 1) * 64;
#pragma unroll
        for (int j = 0; j < 16; j++) {
            int e = j * THREADS + tid;
            int row = e >> 5;
            int cp = e & 31;
            int gr = r0 + row;
            if (gr >= nRows) gr = nRows - 1;
            const float* p;
            if (EDGE) {
                if (src == 0)      p = nf + (size_t)sidx[row] * D;
                else if (src == 1) p = nf + (size_t)ridx[row] * D;
                else               p = ef + (size_t)gr * D;
            } else {
                p = (src == 0 ? nf : (src == 1 ? aggA : aggB)) + (size_t)gr * D;
            }
            float2 v = *(const float2*)(p + col0 + cp * 2);
            uint32_t hp, lp;
            split_pack(v.x, v.y, hp, lp);
            uint32_t off = (uint32_t)(row * AST + 2 * cp) * 2;
            *(uint32_t*)(sm + SM_A  + off) = hp;
            *(uint32_t*)(sm + SM_AL + off) = lp;
        }
        // copy W1 chunk (hi+lo contiguous, 36864B)
        {
            const uint4* srcp = (const uint4*)((const char*)img + (size_t)c * 2 * TILE_B);
            uint4* dst = (uint4*)(sm + SM_B);
            for (int j = tid; j < 2304; j += THREADS) dst[j] = srcp[j];
        }
        __syncthreads();
        gemm_chunk(smb + SM_A, smb + SM_AL, smb + SM_B, smb + SM_BL, acc, wM, wN, lane);
        __syncthreads();
    }

    // ================= h = relu(D1 + b1) -> bf16 hi/lo into H =================
    // H-hi chunk hc at hc*TILE_B (aliases A region), H-lo chunk hc at SM_HLO + hc*TILE_B
    // hc == wN (wN=0 -> cols 0..63, wN=1 -> cols 64..127)
#pragma unroll
    for (int mt = 0; mt < 2; mt++)
#pragma unroll
        for (int nt = 0; nt < 8; nt++)
#pragma unroll
            for (int h = 0; h < 2; h++) {
                int row = wM * 32 + mt * 16 + h * 8 + g4;
                int col = wN * 64 + nt * 8 + 2 * cl;
                float v0 = fmaxf(acc[mt][nt][2 * h]     + cv[col],     0.f);
                float v1 = fmaxf(acc[mt][nt][2 * h + 1] + cv[col + 1], 0.f);
                uint32_t hp, lp;
                split_pack(v0, v1, hp, lp);
                uint32_t off = (uint32_t)(row * AST + (col & 63)) * 2;
                *(uint32_t*)(sm + wN * TILE_B + off) = hp;
                *(uint32_t*)(sm + SM_HLO + wN * TILE_B + off) = lp;
            }
#pragma unroll
    for (int mt = 0; mt < 2; mt++)
#pragma unroll
        for (int nt = 0; nt < 8; nt++)
#pragma unroll
            for (int j = 0; j < 4; j++) acc[mt][nt][j] = 0.f;

    // ================= GEMM2: 2 K-chunks of 64 (A = H) =================
    for (int c2 = 0; c2 < 2; c2++) {
        __syncthreads();   // c2=0: H writes done; c2=1: prev chunk mma done
        {
            const uint4* srcp = (const uint4*)((const char*)img + (size_t)(6 + c2) * 2 * TILE_B);
            uint4* dst = (uint4*)(sm + SM_B);
            for (int j = tid; j < 2304; j += THREADS) dst[j] = srcp[j];
        }
        __syncthreads();
        gemm_chunk(smb + c2 * TILE_B, smb + SM_HLO + c2 * TILE_B,
                   smb + SM_B, smb + SM_BL, acc, wM, wN, lane);
    }
    __syncthreads();       // all mma done; aliases switch to epilogue use

    // ================= bias2 + LN stats =================
#pragma unroll
    for (int mt = 0; mt < 2; mt++)
#pragma unroll
        for (int nt = 0; nt < 8; nt++)
#pragma unroll
            for (int j = 0; j < 4; j++) {
                int col = wN * 64 + nt * 8 + 2 * cl + (j & 1);
                acc[mt][nt][j] += cv[128 + col];
            }
#pragma unroll
    for (int mt = 0; mt < 2; mt++)
#pragma unroll
        for (int h = 0; h < 2; h++) {
            float s = 0.f, q = 0.f;
#pragma unroll
            for (int nt = 0; nt < 8; nt++) {
                float v0 = acc[mt][nt][2 * h], v1 = acc[mt][nt][2 * h + 1];
                s += v0 + v1;
                q += v0 * v0 + v1 * v1;
            }
            s += __shfl_xor_sync(0xffffffffu, s, 1);
            s += __shfl_xor_sync(0xffffffffu, s, 2);
            q += __shfl_xor_sync(0xffffffffu, q, 1);
            q += __shfl_xor_sync(0xffffffffu, q, 2);
            if (cl == 0) {
                int r = wM * 32 + mt * 16 + h * 8 + g4;
                statS[wN * 128 + r] = s;
                statQ[wN * 128 + r] = q;
            }
        }
    __syncthreads();
    if (tid < 128) {
        float s = statS[tid] + statS[128 + tid];
        float q = statQ[tid] + statQ[128 + tid];
        float mean = s * (1.f / D);
        float var = q * (1.f / D) - mean * mean;
        meanv[tid] = mean;
        rstdv[tid] = rsqrtf(var + EPS);
    }
    __syncthreads();

    // ================= LN apply -> hs =================
#pragma unroll
    for (int mt = 0; mt < 2; mt++)
#pragma unroll
        for (int nt = 0; nt < 8; nt++)
#pragma unroll
            for (int j = 0; j < 4; j++) {
                int row = wM * 32 + mt * 16 + ((j >> 1) << 3) + g4;
                int col = wN * 64 + nt * 8 + 2 * cl + (j & 1);
                float y = cv[256 + col] * (acc[mt][nt][j] - meanv[row]) * rstdv[row] + cv[384 + col];
                hs[row * HS_STRIDE + col] = y;
            }
    __syncthreads();

    // ================= epilogue: residual store + atomic scatter =================
#pragma unroll 4
    for (int j = 0; j < (MTILE * D) / THREADS; j++) {
        int e = j * THREADS + tid;
        int r = e >> 7;
        int c = e & 127;
        int gr = r0 + r;
        if (gr < nRows) {
            float y = hs[r * HS_STRIDE + c];
            size_t gi = (size_t)gr * D + c;
            if (EDGE) {
                atomicAdd(&aggOut[(size_t)ridx[r] * D + c], y);
                out[gi] = y + ef[gi];
            } else {
                out[gi] = y + nf[gi];
            }
        }
    }
}

// ---------------- launch ----------------
extern "C" void kernel_launch(void* const* d_in, const int* in_sizes, int n_in,
                              void* d_out, int out_size) {
    (void)in_sizes; (void)n_in; (void)out_size;
    const float* nf   = (const float*)d_in[0];
    const int*   msnd = (const int*)d_in[1];
    const int*   mrcv = (const int*)d_in[2];
    const float* mf   = (const float*)d_in[3];
    const int*   wsnd = (const int*)d_in[4];
    const int*   wrcv = (const int*)d_in[5];
    const float* wf   = (const float*)d_in[6];

    const float* meW1 = (const float*)d_in[7];
    const float* meb1 = (const float*)d_in[8];
    const float* meW2 = (const float*)d_in[9];
    const float* meb2 = (const float*)d_in[10];
    const float* meg  = (const float*)d_in[11];
    const float* mebt = (const float*)d_in[12];

    const float* weW1 = (const float*)d_in[13];
    const float* web1 = (const float*)d_in[14];
    const float* weW2 = (const float*)d_in[15];
    const float* web2 = (const float*)d_in[16];
    const float* weg  = (const float*)d_in[17];
    const float* webt = (const float*)d_in[18];

    const float* nmW1 = (const float*)d_in[19];
    const float* nmb1 = (const float*)d_in[20];
    const float* nmW2 = (const float*)d_in[21];
    const float* nmb2 = (const float*)d_in[22];
    const float* nmg  = (const float*)d_in[23];
    const float* nmbt = (const float*)d_in[24];

    float* out       = (float*)d_out;
    float* out_nodes = out;
    float* out_mesh  = out + (size_t)NN * D;
    float* out_world = out_mesh + (size_t)EM * D;

    float* aggM = nullptr;
    float* aggW = nullptr;
    __nv_bfloat16* img = nullptr;
    cudaGetSymbolAddress((void**)&aggM, g_agg_mesh);
    cudaGetSymbolAddress((void**)&aggW, g_agg_world);
    cudaGetSymbolAddress((void**)&img, g_Wimg);
    __nv_bfloat16* imgME = img;
    __nv_bfloat16* imgWE = img + (size_t)8 * 2 * TILE_H;
    __nv_bfloat16* imgNM = img + (size_t)16 * 2 * TILE_H;

    cudaFuncSetAttribute(mlp_ln_mma_kernel<true>,
                         cudaFuncAttributeMaxDynamicSharedMemorySize, SM_TOTAL);
    cudaFuncSetAttribute(mlp_ln_mma_kernel<false>,
                         cudaFuncAttributeMaxDynamicSharedMemorySize, SM_TOTAL);

    {
        size_t n4 = (size_t)NN * D / 4;
        zero_agg_kernel<<<(int)((n4 + 255) / 256), 256>>>(aggM, aggW);
    }
    prep_kernel<<<256, 256>>>(meW1, meW2, imgME);
    prep_kernel<<<256, 256>>>(weW1, weW2, imgWE);
    prep_kernel<<<256, 256>>>(nmW1, nmW2, imgNM);

    mlp_ln_mma_kernel<true><<<EM / MTILE, THREADS, SM_TOTAL>>>(
        nf, msnd, mrcv, mf, nullptr, nullptr,
        imgME, meb1, meb2, meg, mebt, aggM, out_mesh, EM);

    mlp_ln_mma_kernel<true><<<(EW + MTILE - 1) / MTILE, THREADS, SM_TOTAL>>>(
        nf, wsnd, wrcv, wf, nullptr, nullptr,
        imgWE, web1, web2, weg, webt, aggW, out_world, EW);

    mlp_ln_mma_kernel<false><<<(NN + MTILE - 1) / MTILE, THREADS, SM_TOTAL>>>(
        nf, nullptr, nullptr, nullptr, aggM, aggW,
        imgNM, nmb1, nmb2, nmg, nmbt, nullptr, out_nodes, NN);
}

// round 5
// speedup vs baseline: 3.1661x; 1.0774x over previous
#include <cuda_runtime.h>
#include <cuda_bf16.h>
#include <cstdint>

#define D 128
#define NN 100000
#define EM 400000
#define EW 200000
#define EPS 1e-5f
#define THREADS 256
#define MTILE 128
#define AST 72                   // A/B tile row stride in halves (+4 banks/row skew)
#define TILE_H 9216              // 128*72 halves per half-tile
#define TILE_B 18432             // bytes per half-tile

// ---------------- smem layout (bytes) ----------------
#define SM_A    0
#define SM_AL   18432
#define SM_B    36864
#define SM_BL   55296
#define SM_HLO  73728
#define SM_CV   110592
#define SM_IDX  112640
#define SM_TOTAL 113664
#define HS_STRIDE 132            // hs: 128*132*4 = 67584 bytes at offset 0 (16B aligned rows)

// ---------------- device scratch ----------------
__device__ float g_agg_mesh[(size_t)NN * D];
__device__ float g_agg_world[(size_t)NN * D];
// per mlp: 8 K-chunks (6 for W1, 2 for W2) x {hi,lo} x [128 n][72 k] bf16
__device__ __nv_bfloat16 g_Wimg[3 * 8 * 2 * TILE_H];
// packed pre-split activations: per row 32 x uint4{hi01,hi23,lo01,lo23}
__device__ uint4 g_nfp[(size_t)NN * 32];
__device__ uint4 g_mfp[(size_t)EM * 32];
__device__ uint4 g_wfp[(size_t)EW * 32];
__device__ uint4 g_aggMp[(size_t)NN * 32];
__device__ uint4 g_aggWp[(size_t)NN * 32];

// ---------------- helpers ----------------
__device__ __forceinline__ uint32_t smem_u32(const void* p) {
    uint32_t a;
    asm("{ .reg .u64 t; cvta.to.shared.u64 t, %1; cvt.u32.u64 %0, t; }" : "=r"(a) : "l"(p));
    return a;
}
__device__ __forceinline__ void ldsm_x4(uint32_t r[4], uint32_t addr) {
    asm volatile("ldmatrix.sync.aligned.m8n8.x4.shared.b16 {%0,%1,%2,%3}, [%4];"
        : "=r"(r[0]), "=r"(r[1]), "=r"(r[2]), "=r"(r[3]) : "r"(addr));
}
#define MMA_BF16(d, a, b0, b1) \
    asm volatile("mma.sync.aligned.m16n8k16.row.col.f32.bf16.bf16.f32 " \
        "{%0,%1,%2,%3}, {%4,%5,%6,%7}, {%8,%9}, {%0,%1,%2,%3};" \
        : "+f"((d)[0]), "+f"((d)[1]), "+f"((d)[2]), "+f"((d)[3]) \
        : "r"((a)[0]), "r"((a)[1]), "r"((a)[2]), "r"((a)[3]), "r"(b0), "r"(b1))

__device__ __forceinline__ void split_pack(float x, float y, uint32_t& hp, uint32_t& lp) {
    __nv_bfloat16 h0 = __float2bfloat16(x);
    __nv_bfloat16 h1 = __float2bfloat16(y);
    __nv_bfloat16 l0 = __float2bfloat16(x - __bfloat162float(h0));
    __nv_bfloat16 l1 = __float2bfloat16(y - __bfloat162float(h1));
    hp = (uint32_t)__bfloat16_as_ushort(h0) | ((uint32_t)__bfloat16_as_ushort(h1) << 16);
    lp = (uint32_t)__bfloat16_as_ushort(l0) | ((uint32_t)__bfloat16_as_ushort(l1) << 16);
}

// one K=64 chunk: warp tile 32 rows (wM) x 64 cols (wN); 3-way bf16 split
__device__ __forceinline__ void gemm_chunk(uint32_t aH, uint32_t aL,
                                           uint32_t bH, uint32_t bL,
                                           float acc[2][8][4],
                                           int wM, int wN, int lane) {
    const int i = lane & 7, sel = lane >> 3;
    const int selA = ((sel & 1) << 3) * AST + ((sel >> 1) << 3);
    const int selB = ((sel >> 1) << 3) * AST + ((sel & 1) << 3);
#pragma unroll
    for (int ks = 0; ks < 4; ks++) {
        const int k0 = ks * 16;
        uint32_t ah[2][4], al[2][4];
#pragma unroll
        for (int mt = 0; mt < 2; mt++) {
            uint32_t off = (uint32_t)((wM * 32 + mt * 16 + i) * AST + k0 + selA) * 2;
            ldsm_x4(ah[mt], aH + off);
            ldsm_x4(al[mt], aL + off);
        }
#pragma unroll
        for (int p = 0; p < 4; p++) {
            uint32_t offb = (uint32_t)((wN * 64 + p * 16 + i) * AST + k0 + selB) * 2;
            uint32_t bh[4], bl[4];
            ldsm_x4(bh, bH + offb);
            ldsm_x4(bl, bL + offb);
#pragma unroll
            for (int h = 0; h < 2; h++) {
                const int nt = 2 * p + h;
#pragma unroll
                for (int mt = 0; mt < 2; mt++) {
                    MMA_BF16(acc[mt][nt], ah[mt], bh[2 * h], bh[2 * h + 1]);
                    MMA_BF16(acc[mt][nt], ah[mt], bl[2 * h], bl[2 * h + 1]);
                    MMA_BF16(acc[mt][nt], al[mt], bh[2 * h], bh[2 * h + 1]);
                }
            }
        }
    }
}

// ---------------- prep kernels ----------------
__global__ void prep_kernel(const float* __restrict__ W1, const float* __restrict__ W2,
                            __nv_bfloat16* __restrict__ img) {
    int idx = blockIdx.x * blockDim.x + threadIdx.x;   // 0..65535
    int chunk = idx >> 13;
    int rem = idx & 8191;
    int n = rem >> 6;
    int kk = rem & 63;
    float v;
    if (chunk < 6) v = W1[(size_t)(chunk * 64 + kk) * 128 + n];
    else           v = W2[(size_t)((chunk - 6) * 64 + kk) * 128 + n];
    __nv_bfloat16 hi = __float2bfloat16(v);
    __nv_bfloat16 lo = __float2bfloat16(v - __bfloat162float(hi));
    size_t base = (size_t)chunk * 2 * TILE_H + (size_t)n * AST + kk;
    img[base] = hi;
    img[base + TILE_H] = lo;
}

// split fp32 -> packed {hi01,hi23,lo01,lo23} per 4-col quad
__global__ void split_kernel(const float* __restrict__ in, uint4* __restrict__ out, size_t nq) {
    size_t i = (size_t)blockIdx.x * blockDim.x + threadIdx.x;
    if (i < nq) {
        float4 v = ((const float4*)in)[i];
        uint32_t h0, l0, h1, l1;
        split_pack(v.x, v.y, h0, l0);
        split_pack(v.z, v.w, h1, l1);
        out[i] = make_uint4(h0, h1, l0, l1);
    }
}

__global__ void zero_agg_kernel(float* __restrict__ aggM, float* __restrict__ aggW) {
    size_t i = (size_t)blockIdx.x * blockDim.x + threadIdx.x;
    size_t n4 = (size_t)NN * D / 4;
    float4 z = make_float4(0.f, 0.f, 0.f, 0.f);
    if (i < n4) { ((float4*)aggM)[i] = z; ((float4*)aggW)[i] = z; }
}

// ---------------- fused MLP+LN block kernel ----------------
// A row sources (packed): src0 (rows sidx/own), src1 (ridx/own), src2 (own row).
// res = fp32 residual source (edge features / node features), also streamed in epilogue.
template <bool EDGE>
__global__ void __launch_bounds__(THREADS, 2)
mlp_ln_mma_kernel(const uint4* __restrict__ src0p,
                  const uint4* __restrict__ src1p,
                  const uint4* __restrict__ src2p,
                  const float* __restrict__ res,
                  const int*   __restrict__ senders,
                  const int*   __restrict__ receivers,
                  const __nv_bfloat16* __restrict__ img,
                  const float* __restrict__ b1, const float* __restrict__ b2,
                  const float* __restrict__ gam, const float* __restrict__ bet,
                  float* __restrict__ aggOut,
                  float* __restrict__ out,
                  int nRows) {
    extern __shared__ char sm[];
    float* cv    = (float*)(sm + SM_CV);
    int*   sidx  = (int*)(sm + SM_IDX);
    int*   ridx  = sidx + MTILE;
    float* statS = (float*)(sm + SM_HLO);           // epilogue aliases (H-lo dead)
    float* statQ = statS + 256;
    float* meanv = statQ + 256;
    float* rstdv = meanv + 128;
    float* hs    = (float*)sm;                      // aliases A+B regions after GEMM2

    const uint32_t smb = smem_u32(sm);
    const int tid = threadIdx.x;
    const int wid = tid >> 5;
    const int lane = tid & 31;
    const int wM = wid >> 1;
    const int wN = wid & 1;
    const int g4 = lane >> 2, cl = lane & 3;
    const int r0 = blockIdx.x * MTILE;

    if (tid < 128) {
        cv[tid]       = b1[tid];
        cv[128 + tid] = b2[tid];
        cv[256 + tid] = gam[tid];
        cv[384 + tid] = bet[tid];
        int rr = r0 + tid;
        if (rr >= nRows) rr = nRows - 1;
        sidx[tid] = EDGE ? senders[rr] : rr;
        ridx[tid] = EDGE ? receivers[rr] : rr;
    }
    __syncthreads();

    float acc[2][8][4];
#pragma unroll
    for (int mt = 0; mt < 2; mt++)
#pragma unroll
        for (int nt = 0; nt < 8; nt++)
#pragma unroll
            for (int j = 0; j < 4; j++) acc[mt][nt][j] = 0.f;

    // ================= GEMM1: 6 K-chunks of 64 =================
    for (int c = 0; c < 6; c++) {
        const int src = c >> 1;
        const int q0 = (c & 1) * 16;       // quad-col offset within row (16 quads = 64 cols)
        // gather packed A chunk: 128 rows x 16 quads
#pragma unroll
        for (int j = 0; j < 8; j++) {
            int e = j * THREADS + tid;
            int row = e >> 4;
            int qc = e & 15;
            int gr = r0 + row;
            if (gr >= nRows) gr = nRows - 1;
            const uint4* p;
            if (src == 0)      p = src0p + (size_t)sidx[row] * 32;
            else if (src == 1) p = src1p + (size_t)ridx[row] * 32;
            else               p = src2p + (size_t)gr * 32;
            uint4 v = p[q0 + qc];
            uint32_t off = (uint32_t)(row * AST + qc * 4) * 2;
            *(uint2*)(sm + SM_A  + off) = make_uint2(v.x, v.y);
            *(uint2*)(sm + SM_AL + off) = make_uint2(v.z, v.w);
        }
        // copy W1 chunk (hi+lo contiguous, 36864B)
        {
            const uint4* srcp = (const uint4*)((const char*)img + (size_t)c * 2 * TILE_B);
            uint4* dst = (uint4*)(sm + SM_B);
            for (int j = tid; j < 2304; j += THREADS) dst[j] = srcp[j];
        }
        __syncthreads();
        gemm_chunk(smb + SM_A, smb + SM_AL, smb + SM_B, smb + SM_BL, acc, wM, wN, lane);
        __syncthreads();
    }

    // ================= h = relu(D1 + b1) -> bf16 hi/lo into H =================
#pragma unroll
    for (int mt = 0; mt < 2; mt++)
#pragma unroll
        for (int nt = 0; nt < 8; nt++)
#pragma unroll
            for (int h = 0; h < 2; h++) {
                int row = wM * 32 + mt * 16 + h * 8 + g4;
                int col = wN * 64 + nt * 8 + 2 * cl;
                float v0 = fmaxf(acc[mt][nt][2 * h]     + cv[col],     0.f);
                float v1 = fmaxf(acc[mt][nt][2 * h + 1] + cv[col + 1], 0.f);
                uint32_t hp, lp;
                split_pack(v0, v1, hp, lp);
                uint32_t off = (uint32_t)(row * AST + (col & 63)) * 2;
                *(uint32_t*)(sm + wN * TILE_B + off) = hp;
                *(uint32_t*)(sm + SM_HLO + wN * TILE_B + off) = lp;
            }
#pragma unroll
    for (int mt = 0; mt < 2; mt++)
#pragma unroll
        for (int nt = 0; nt < 8; nt++)
#pragma unroll
            for (int j = 0; j < 4; j++) acc[mt][nt][j] = 0.f;

    // ================= GEMM2: 2 K-chunks of 64 (A = H) =================
    for (int c2 = 0; c2 < 2; c2++) {
        __syncthreads();
        {
            const uint4* srcp = (const uint4*)((const char*)img + (size_t)(6 + c2) * 2 * TILE_B);
            uint4* dst = (uint4*)(sm + SM_B);
            for (int j = tid; j < 2304; j += THREADS) dst[j] = srcp[j];
        }
        __syncthreads();
        gemm_chunk(smb + c2 * TILE_B, smb + SM_HLO + c2 * TILE_B,
                   smb + SM_B, smb + SM_BL, acc, wM, wN, lane);
    }
    __syncthreads();

    // ================= bias2 + LN stats =================
#pragma unroll
    for (int mt = 0; mt < 2; mt++)
#pragma unroll
        for (int nt = 0; nt < 8; nt++)
#pragma unroll
            for (int j = 0; j < 4; j++) {
                int col = wN * 64 + nt * 8 + 2 * cl + (j & 1);
                acc[mt][nt][j] += cv[128 + col];
            }
#pragma unroll
    for (int mt = 0; mt < 2; mt++)
#pragma unroll
        for (int h = 0; h < 2; h++) {
            float s = 0.f, q = 0.f;
#pragma unroll
            for (int nt = 0; nt < 8; nt++) {
                float v0 = acc[mt][nt][2 * h], v1 = acc[mt][nt][2 * h + 1];
                s += v0 + v1;
                q += v0 * v0 + v1 * v1;
            }
            s += __shfl_xor_sync(0xffffffffu, s, 1);
            s += __shfl_xor_sync(0xffffffffu, s, 2);
            q += __shfl_xor_sync(0xffffffffu, q, 1);
            q += __shfl_xor_sync(0xffffffffu, q, 2);
            if (cl == 0) {
                int r = wM * 32 + mt * 16 + h * 8 + g4;
                statS[wN * 128 + r] = s;
                statQ[wN * 128 + r] = q;
            }
        }
    __syncthreads();
    if (tid < 128) {
        float s = statS[tid] + statS[128 + tid];
        float q = statQ[tid] + statQ[128 + tid];
        float mean = s * (1.f / D);
        float var = q * (1.f / D) - mean * mean;
        meanv[tid] = mean;
        rstdv[tid] = rsqrtf(var + EPS);
    }
    __syncthreads();

    // ================= LN apply -> hs =================
#pragma unroll
    for (int mt = 0; mt < 2; mt++)
#pragma unroll
        for (int nt = 0; nt < 8; nt++)
#pragma unroll
            for (int j = 0; j < 4; j++) {
                int row = wM * 32 + mt * 16 + ((j >> 1) << 3) + g4;
                int col = wN * 64 + nt * 8 + 2 * cl + (j & 1);
                float y = cv[256 + col] * (acc[mt][nt][j] - meanv[row]) * rstdv[row] + cv[384 + col];
                hs[row * HS_STRIDE + col] = y;
            }
    __syncthreads();

    // ================= epilogue: float4 residual store + float4 atomic scatter =================
#pragma unroll
    for (int j = 0; j < (MTILE * 32) / THREADS; j++) {     // 128 rows x 32 quads
        int e = j * THREADS + tid;
        int r = e >> 5;
        int q = e & 31;
        int gr = r0 + r;
        if (gr < nRows) {
            float4 y = *(const float4*)&hs[r * HS_STRIDE + q * 4];
            size_t gi = (size_t)gr * D + q * 4;
            if (EDGE) {
                atomicAdd((float4*)&aggOut[(size_t)ridx[r] * D + q * 4], y);
            }
            float4 rv = *(const float4*)&res[gi];
            float4 o = make_float4(y.x + rv.x, y.y + rv.y, y.z + rv.z, y.w + rv.w);
            *(float4*)&out[gi] = o;
        }
    }
}

// ---------------- launch ----------------
extern "C" void kernel_launch(void* const* d_in, const int* in_sizes, int n_in,
                              void* d_out, int out_size) {
    (void)in_sizes; (void)n_in; (void)out_size;
    const float* nf   = (const float*)d_in[0];
    const int*   msnd = (const int*)d_in[1];
    const int*   mrcv = (const int*)d_in[2];
    const float* mf   = (const float*)d_in[3];
    const int*   wsnd = (const int*)d_in[4];
    const int*   wrcv = (const int*)d_in[5];
    const float* wf   = (const float*)d_in[6];

    const float* meW1 = (const float*)d_in[7];
    const float* meb1 = (const float*)d_in[8];
    const float* meW2 = (const float*)d_in[9];
    const float* meb2 = (const float*)d_in[10];
    const float* meg  = (const float*)d_in[11];
    const float* mebt = (const float*)d_in[12];

    const float* weW1 = (const float*)d_in[13];
    const float* web1 = (const float*)d_in[14];
    const float* weW2 = (const float*)d_in[15];
    const float* web2 = (const float*)d_in[16];
    const float* weg  = (const float*)d_in[17];
    const float* webt = (const float*)d_in[18];

    const float* nmW1 = (const float*)d_in[19];
    const float* nmb1 = (const float*)d_in[20];
    const float* nmW2 = (const float*)d_in[21];
    const float* nmb2 = (const float*)d_in[22];
    const float* nmg  = (const float*)d_in[23];
    const float* nmbt = (const float*)d_in[24];

    float* out       = (float*)d_out;
    float* out_nodes = out;
    float* out_mesh  = out + (size_t)NN * D;
    float* out_world = out_mesh + (size_t)EM * D;

    float* aggM = nullptr;  float* aggW = nullptr;
    __nv_bfloat16* img = nullptr;
    uint4 *nfp = nullptr, *mfp = nullptr, *wfp = nullptr, *aMp = nullptr, *aWp = nullptr;
    cudaGetSymbolAddress((void**)&aggM, g_agg_mesh);
    cudaGetSymbolAddress((void**)&aggW, g_agg_world);
    cudaGetSymbolAddress((void**)&img, g_Wimg);
    cudaGetSymbolAddress((void**)&nfp, g_nfp);
    cudaGetSymbolAddress((void**)&mfp, g_mfp);
    cudaGetSymbolAddress((void**)&wfp, g_wfp);
    cudaGetSymbolAddress((void**)&aMp, g_aggMp);
    cudaGetSymbolAddress((void**)&aWp, g_aggWp);
    __nv_bfloat16* imgME = img;
    __nv_bfloat16* imgWE = img + (size_t)8 * 2 * TILE_H;
    __nv_bfloat16* imgNM = img + (size_t)16 * 2 * TILE_H;

    cudaFuncSetAttribute(mlp_ln_mma_kernel<true>,
                         cudaFuncAttributeMaxDynamicSharedMemorySize, SM_TOTAL);
    cudaFuncSetAttribute(mlp_ln_mma_kernel<false>,
                         cudaFuncAttributeMaxDynamicSharedMemorySize, SM_TOTAL);

    {
        size_t n4 = (size_t)NN * D / 4;
        zero_agg_kernel<<<(int)((n4 + 255) / 256), 256>>>(aggM, aggW);
    }
    prep_kernel<<<256, 256>>>(meW1, meW2, imgME);
    prep_kernel<<<256, 256>>>(weW1, weW2, imgWE);
    prep_kernel<<<256, 256>>>(nmW1, nmW2, imgNM);

    {
        size_t nq;
        nq = (size_t)NN * 32; split_kernel<<<(int)((nq + 255) / 256), 256>>>(nf, nfp, nq);
        nq = (size_t)EM * 32; split_kernel<<<(int)((nq + 255) / 256), 256>>>(mf, mfp, nq);
        nq = (size_t)EW * 32; split_kernel<<<(int)((nq + 255) / 256), 256>>>(wf, wfp, nq);
    }

    mlp_ln_mma_kernel<true><<<EM / MTILE, THREADS, SM_TOTAL>>>(
        nfp, nfp, mfp, mf, msnd, mrcv,
        imgME, meb1, meb2, meg, mebt, aggM, out_mesh, EM);

    mlp_ln_mma_kernel<true><<<(EW + MTILE - 1) / MTILE, THREADS, SM_TOTAL>>>(
        nfp, nfp, wfp, wf, wsnd, wrcv,
        imgWE, web1, web2, weg, webt, aggW, out_world, EW);

    {
        size_t nq = (size_t)NN * 32;
        split_kernel<<<(int)((nq + 255) / 256), 256>>>(aggM, aMp, nq);
        split_kernel<<<(int)((nq + 255) / 256), 256>>>(aggW, aWp, nq);
    }

    mlp_ln_mma_kernel<false><<<(NN + MTILE - 1) / MTILE, THREADS, SM_TOTAL>>>(
        nfp, aMp, aWp, nf, nullptr, nullptr,
        imgNM, nmb1, nmb2, nmg, nmbt, nullptr, out_nodes, NN);
}